// round 1
// baseline (speedup 1.0000x reference)
#include <cuda_runtime.h>

// Problem constants (fixed by setup_inputs): 64 graphs x 2048 rows x 128 dim.
#define NG 64
#define LL 2048
#define DD 128
#define NSPLIT 8
#define RPS (LL / NSPLIT)   // rows per gram split = 256
#define SMS 132             // padded smem row stride (floats), keeps 16B alignment

// Scratch (device globals; no allocation at runtime)
__device__ float g_gram_part[NG][NSPLIT][DD * DD];  // 32 MB
__device__ float g_gram[NG][DD * DD];               // 4 MB
__device__ float g_w2t[DD * DD];                    // w2t[k][p] = mp_w[p][k]^2

// ---------------------------------------------------------------------------
// Kernel 1: W2 transpose+square
// ---------------------------------------------------------------------------
__global__ void w2_kernel(const float* __restrict__ mp_w) {
    int idx = blockIdx.x * blockDim.x + threadIdx.x;
    if (idx < DD * DD) {
        int p = idx / DD, k = idx % DD;
        float w = mp_w[p * DD + k];
        g_w2t[k * DD + p] = w * w;
    }
}

// ---------------------------------------------------------------------------
// Kernel 2: per-graph Gram partials.  block = one (graph, K-split).
// G_part[g][sp] = X_chunk^T X_chunk  over 256 rows.  8x8 register tile/thread.
// ---------------------------------------------------------------------------
__global__ void __launch_bounds__(256) gram_kernel(const float* __restrict__ feats) {
    __shared__ float Xs[64][DD];   // 32 KB
    int g  = blockIdx.x / NSPLIT;
    int sp = blockIdx.x % NSPLIT;
    const float* X = feats + ((size_t)g * LL + (size_t)sp * RPS) * DD;

    int t  = threadIdx.x;
    int tx = t & 15, ty = t >> 4;
    int i0 = ty * 8, j0 = tx * 8;

    float acc[8][8];
#pragma unroll
    for (int i = 0; i < 8; i++)
#pragma unroll
        for (int j = 0; j < 8; j++) acc[i][j] = 0.f;

    for (int c = 0; c < RPS; c += 64) {
        const float4* src = (const float4*)(X + (size_t)c * DD);
        float4* dst = (float4*)&Xs[0][0];
#pragma unroll
        for (int q = 0; q < 8; q++) dst[t + 256 * q] = src[t + 256 * q];
        __syncthreads();

#pragma unroll 4
        for (int r = 0; r < 64; r++) {
            float a[8], b[8];
            *(float4*)&a[0] = *(const float4*)&Xs[r][i0];
            *(float4*)&a[4] = *(const float4*)&Xs[r][i0 + 4];
            *(float4*)&b[0] = *(const float4*)&Xs[r][j0];
            *(float4*)&b[4] = *(const float4*)&Xs[r][j0 + 4];
#pragma unroll
            for (int ii = 0; ii < 8; ii++)
#pragma unroll
                for (int jj = 0; jj < 8; jj++)
                    acc[ii][jj] = fmaf(a[ii], b[jj], acc[ii][jj]);
        }
        __syncthreads();
    }

    float* outp = g_gram_part[g][sp];
#pragma unroll
    for (int ii = 0; ii < 8; ii++) {
        float4 o0 = make_float4(acc[ii][0], acc[ii][1], acc[ii][2], acc[ii][3]);
        float4 o1 = make_float4(acc[ii][4], acc[ii][5], acc[ii][6], acc[ii][7]);
        *(float4*)&outp[(i0 + ii) * DD + j0]     = o0;
        *(float4*)&outp[(i0 + ii) * DD + j0 + 4] = o1;
    }
}

// ---------------------------------------------------------------------------
// Kernel 3: reduce partials (deterministic order)
// ---------------------------------------------------------------------------
__global__ void reduce_kernel() {
    int idx = blockIdx.x * blockDim.x + threadIdx.x;  // 0 .. NG*DD*DD-1
    int g = idx >> 14;
    int e = idx & 16383;
    float s = 0.f;
#pragma unroll
    for (int sp = 0; sp < NSPLIT; sp++) s += g_gram_part[g][sp][e];
    g_gram[g][e] = s;
}

// ---------------------------------------------------------------------------
// Kernel 4: fused  V2 = X @ G_partner  ->  multi-perspective match.
// block = one (graph-side g in 0..63, 128-row tile).  256 threads.
// smem: Xt (X transposed, [k][l]), Bs (G then W2t), Vt (V2 transposed [k][l]).
// ---------------------------------------------------------------------------
#define FUSED_SMEM (3 * 128 * SMS * 4)

__global__ void __launch_bounds__(256) fused_kernel(const float* __restrict__ feats,
                                                    float* __restrict__ out) {
    extern __shared__ float sm[];
    float* Xt = sm;
    float* Bs = sm + 128 * SMS;
    float* Vt = sm + 2 * 128 * SMS;

    int blk  = blockIdx.x;
    int g    = blk >> 4;     // graph-side 0..63
    int tile = blk & 15;     // row tile 0..15
    const float* X  = feats + ((size_t)g * LL + (size_t)tile * 128) * DD;
    const float* Gp = g_gram[g ^ 1];   // partner's Gram

    int t  = threadIdx.x;
    int tx = t & 15, ty = t >> 4;
    int l0 = ty * 8, j0 = tx * 8;

    // Load X transposed into Xt[k][l]; G row-major into Bs[k][j].
#pragma unroll
    for (int q = 0; q < 16; q++) {
        int idx = t + 256 * q;        // float4 index 0..4095
        int l   = idx >> 5;           // row 0..127
        int k4  = idx & 31;           // float4-col 0..31
        float4 v = ((const float4*)X)[idx];
        int k = k4 * 4;
        Xt[(k + 0) * SMS + l] = v.x;
        Xt[(k + 1) * SMS + l] = v.y;
        Xt[(k + 2) * SMS + l] = v.z;
        Xt[(k + 3) * SMS + l] = v.w;
        ((float4*)&Bs[l * SMS])[k4] = ((const float4*)Gp)[idx];
    }
    __syncthreads();

    // Stage 1: V2[l][j] = sum_k X[l][k] * G[k][j]
    float acc[8][8];
#pragma unroll
    for (int i = 0; i < 8; i++)
#pragma unroll
        for (int j = 0; j < 8; j++) acc[i][j] = 0.f;

#pragma unroll 4
    for (int k = 0; k < 128; k++) {
        float a[8], b[8];
        *(float4*)&a[0] = *(const float4*)&Xt[k * SMS + l0];
        *(float4*)&a[4] = *(const float4*)&Xt[k * SMS + l0 + 4];
        *(float4*)&b[0] = *(const float4*)&Bs[k * SMS + j0];
        *(float4*)&b[4] = *(const float4*)&Bs[k * SMS + j0 + 4];
#pragma unroll
        for (int ii = 0; ii < 8; ii++)
#pragma unroll
            for (int jj = 0; jj < 8; jj++)
                acc[ii][jj] = fmaf(a[ii], b[jj], acc[ii][jj]);
    }
    __syncthreads();   // everyone done reading Bs (G)

    // Write V2 transposed: Vt[j][l]
#pragma unroll
    for (int jj = 0; jj < 8; jj++) {
        float4 v0 = make_float4(acc[0][jj], acc[1][jj], acc[2][jj], acc[3][jj]);
        float4 v1 = make_float4(acc[4][jj], acc[5][jj], acc[6][jj], acc[7][jj]);
        *(float4*)&Vt[(j0 + jj) * SMS + l0]     = v0;
        *(float4*)&Vt[(j0 + jj) * SMS + l0 + 4] = v1;
    }
    // Load W2t into Bs
#pragma unroll
    for (int q = 0; q < 16; q++) {
        int idx = t + 256 * q;
        int r = idx >> 5, c4 = idx & 31;
        ((float4*)&Bs[r * SMS])[c4] = ((const float4*)g_w2t)[idx];
    }
    __syncthreads();

    // Stage 2: three GEMMs sharing one K loop; 8 rows x 4 persp / thread, 2 halves.
    float* outrow = out + ((size_t)g * LL + (size_t)tile * 128) * DD;
#pragma unroll 1
    for (int ph = 0; ph < 2; ph++) {
        int pc = ph * 64 + tx * 4;
        float aN[8][4], a1[8][4], a2[8][4];
#pragma unroll
        for (int i = 0; i < 8; i++)
#pragma unroll
            for (int j = 0; j < 4; j++) { aN[i][j] = 0.f; a1[i][j] = 0.f; a2[i][j] = 0.f; }

#pragma unroll 2
        for (int k = 0; k < 128; k++) {
            float x[8], v[8], w[4];
            *(float4*)&x[0] = *(const float4*)&Xt[k * SMS + l0];
            *(float4*)&x[4] = *(const float4*)&Xt[k * SMS + l0 + 4];
            *(float4*)&v[0] = *(const float4*)&Vt[k * SMS + l0];
            *(float4*)&v[4] = *(const float4*)&Vt[k * SMS + l0 + 4];
            *(float4*)&w[0] = *(const float4*)&Bs[k * SMS + pc];
#pragma unroll
            for (int ii = 0; ii < 8; ii++) {
                float en = x[ii] * v[ii];
                float e1 = x[ii] * x[ii];
                float e2 = v[ii] * v[ii];
#pragma unroll
                for (int jj = 0; jj < 4; jj++) {
                    aN[ii][jj] = fmaf(en, w[jj], aN[ii][jj]);
                    a1[ii][jj] = fmaf(e1, w[jj], a1[ii][jj]);
                    a2[ii][jj] = fmaf(e2, w[jj], a2[ii][jj]);
                }
            }
        }

#pragma unroll
        for (int ii = 0; ii < 8; ii++) {
            float o[4];
#pragma unroll
            for (int jj = 0; jj < 4; jj++) {
                float denom = sqrtf(a1[ii][jj] * a2[ii][jj]);
                o[jj] = aN[ii][jj] / fmaxf(denom, 1e-8f);
            }
            *(float4*)&outrow[(l0 + ii) * DD + pc] = make_float4(o[0], o[1], o[2], o[3]);
        }
    }
}

// ---------------------------------------------------------------------------
extern "C" void kernel_launch(void* const* d_in, const int* in_sizes, int n_in,
                              void* d_out, int out_size) {
    const float* feats = (const float*)d_in[0];
    const float* mp_w  = (const float*)d_in[1];
    float* out = (float*)d_out;

    cudaFuncSetAttribute(fused_kernel, cudaFuncAttributeMaxDynamicSharedMemorySize,
                         FUSED_SMEM);

    w2_kernel<<<64, 256>>>(mp_w);
    gram_kernel<<<NG * NSPLIT, 256>>>(feats);
    reduce_kernel<<<(NG * DD * DD) / 256, 256>>>();
    fused_kernel<<<NG * (LL / 128), 256, FUSED_SMEM>>>(feats, out);
}

// round 2
// speedup vs baseline: 1.0300x; 1.0300x over previous
#include <cuda_runtime.h>

// Problem constants (fixed by setup_inputs): 64 graphs x 2048 rows x 128 dim.
#define NG 64
#define LL 2048
#define DD 128
#define NSPLIT 8
#define RPS (LL / NSPLIT)   // rows per gram split = 256
#define SMS 132             // padded smem row stride (floats), 16B-aligned

typedef unsigned long long u64;

// ---- packed fp32x2 helpers (SASS FFMA2 path, PTX-only) ---------------------
__device__ __forceinline__ u64 pack2(float x) {
    u64 r; asm("mov.b64 %0, {%1, %1};" : "=l"(r) : "f"(x)); return r;
}
__device__ __forceinline__ u64 ffma2(u64 a, u64 b, u64 c) {
    u64 d; asm("fma.rn.f32x2 %0, %1, %2, %3;" : "=l"(d) : "l"(a), "l"(b), "l"(c));
    return d;
}
__device__ __forceinline__ u64 fmul2(u64 a, u64 b) {
    u64 d; asm("mul.rn.f32x2 %0, %1, %2;" : "=l"(d) : "l"(a), "l"(b)); return d;
}
__device__ __forceinline__ float2 unpk(u64 v) {
    float lo, hi; asm("mov.b64 {%0, %1}, %2;" : "=f"(lo), "=f"(hi) : "l"(v));
    return make_float2(lo, hi);
}

// Scratch (device globals; no allocation at runtime)
__device__ float g_gram_part[NG][NSPLIT][DD * DD];  // 32 MB
__device__ float g_gram[NG][DD * DD];               // 4 MB
__device__ float g_w2t[DD * DD];                    // w2t[k][p] = mp_w[p][k]^2

// ---------------------------------------------------------------------------
// Kernel 1: W2 transpose+square
// ---------------------------------------------------------------------------
__global__ void w2_kernel(const float* __restrict__ mp_w) {
    int idx = blockIdx.x * blockDim.x + threadIdx.x;
    if (idx < DD * DD) {
        int p = idx / DD, k = idx % DD;
        float w = mp_w[p * DD + k];
        g_w2t[k * DD + p] = w * w;
    }
}

// ---------------------------------------------------------------------------
// Kernel 2: per-graph Gram partials.  block = one (graph, K-split).
// 8 rows x 8 cols / thread, f32x2 packed along columns.
// ---------------------------------------------------------------------------
__global__ void __launch_bounds__(256) gram_kernel(const float* __restrict__ feats) {
    __shared__ __align__(16) float Xs[64][DD];   // 32 KB
    int g  = blockIdx.x / NSPLIT;
    int sp = blockIdx.x % NSPLIT;
    const float* X = feats + ((size_t)g * LL + (size_t)sp * RPS) * DD;

    int t  = threadIdx.x;
    int tx = t & 15, ty = t >> 4;
    int i0 = ty * 8, j0 = tx * 8;

    u64 acc[8][4];
#pragma unroll
    for (int i = 0; i < 8; i++)
#pragma unroll
        for (int j = 0; j < 4; j++) acc[i][j] = 0ull;

    for (int c = 0; c < RPS; c += 64) {
        const float4* src = (const float4*)(X + (size_t)c * DD);
        float4* dst = (float4*)&Xs[0][0];
#pragma unroll
        for (int q = 0; q < 8; q++) dst[t + 256 * q] = src[t + 256 * q];
        __syncthreads();

#pragma unroll 4
        for (int r = 0; r < 64; r++) {
            float4 av0 = *(const float4*)&Xs[r][i0];
            float4 av1 = *(const float4*)&Xs[r][i0 + 4];
            float a[8] = {av0.x, av0.y, av0.z, av0.w, av1.x, av1.y, av1.z, av1.w};
            u64 ap[8];
#pragma unroll
            for (int i = 0; i < 8; i++) ap[i] = pack2(a[i]);
            ulonglong2 b0 = *(const ulonglong2*)&Xs[r][j0];
            ulonglong2 b1 = *(const ulonglong2*)&Xs[r][j0 + 4];
            u64 bb[4] = {b0.x, b0.y, b1.x, b1.y};
#pragma unroll
            for (int ii = 0; ii < 8; ii++)
#pragma unroll
                for (int jj = 0; jj < 4; jj++)
                    acc[ii][jj] = ffma2(ap[ii], bb[jj], acc[ii][jj]);
        }
        __syncthreads();
    }

    float* outp = g_gram_part[g][sp];
#pragma unroll
    for (int ii = 0; ii < 8; ii++) {
        float2 p0 = unpk(acc[ii][0]), p1 = unpk(acc[ii][1]);
        float2 p2 = unpk(acc[ii][2]), p3 = unpk(acc[ii][3]);
        *(float4*)&outp[(i0 + ii) * DD + j0]     = make_float4(p0.x, p0.y, p1.x, p1.y);
        *(float4*)&outp[(i0 + ii) * DD + j0 + 4] = make_float4(p2.x, p2.y, p3.x, p3.y);
    }
}

// ---------------------------------------------------------------------------
// Kernel 3: reduce partials (deterministic order)
// ---------------------------------------------------------------------------
__global__ void reduce_kernel() {
    int idx = blockIdx.x * blockDim.x + threadIdx.x;
    int g = idx >> 14;
    int e = idx & 16383;
    float s = 0.f;
#pragma unroll
    for (int sp = 0; sp < NSPLIT; sp++) s += g_gram_part[g][sp][e];
    g_gram[g][e] = s;
}

// ---------------------------------------------------------------------------
// Kernel 4: fused  V2 = X @ G_partner  ->  multi-perspective match.
// block = (graph-side, 128-row tile), 256 threads, f32x2 throughout.
// ---------------------------------------------------------------------------
#define FUSED_SMEM (3 * 128 * SMS * 4)

__global__ void __launch_bounds__(256) fused_kernel(const float* __restrict__ feats,
                                                    float* __restrict__ out) {
    extern __shared__ float sm[];
    float* Xt = sm;                  // X transposed [k][l]
    float* Bs = sm + 128 * SMS;      // G, then W2t   [k][j]
    float* Vt = sm + 2 * 128 * SMS;  // V2 transposed [k][l]

    int blk  = blockIdx.x;
    int g    = blk >> 4;     // graph-side 0..63
    int tile = blk & 15;     // row tile 0..15
    const float* X  = feats + ((size_t)g * LL + (size_t)tile * 128) * DD;
    const float* Gp = g_gram[g ^ 1];   // partner's Gram (symmetric)

    int t  = threadIdx.x;
    int tx = t & 15, ty = t >> 4;
    int l0 = ty * 8, j0 = tx * 8;

    // Load X transposed into Xt[k][l]; G row-major into Bs[k][j].
#pragma unroll
    for (int q = 0; q < 16; q++) {
        int idx = t + 256 * q;        // float4 index 0..4095
        int l   = idx >> 5;
        int k4  = idx & 31;
        float4 v = ((const float4*)X)[idx];
        int k = k4 * 4;
        Xt[(k + 0) * SMS + l] = v.x;
        Xt[(k + 1) * SMS + l] = v.y;
        Xt[(k + 2) * SMS + l] = v.z;
        Xt[(k + 3) * SMS + l] = v.w;
        *(float4*)&Bs[l * SMS + k] = ((const float4*)Gp)[idx];
    }
    __syncthreads();

    // Stage 1: V2[l][j] = sum_k X[l][k] * G[k][j]   (f32x2 packed along j)
    u64 acc[8][4];
#pragma unroll
    for (int i = 0; i < 8; i++)
#pragma unroll
        for (int j = 0; j < 4; j++) acc[i][j] = 0ull;

#pragma unroll 2
    for (int k = 0; k < 128; k++) {
        float4 av0 = *(const float4*)&Xt[k * SMS + l0];
        float4 av1 = *(const float4*)&Xt[k * SMS + l0 + 4];
        float a[8] = {av0.x, av0.y, av0.z, av0.w, av1.x, av1.y, av1.z, av1.w};
        u64 ap[8];
#pragma unroll
        for (int i = 0; i < 8; i++) ap[i] = pack2(a[i]);
        ulonglong2 b0 = *(const ulonglong2*)&Bs[k * SMS + j0];
        ulonglong2 b1 = *(const ulonglong2*)&Bs[k * SMS + j0 + 4];
        u64 bb[4] = {b0.x, b0.y, b1.x, b1.y};
#pragma unroll
        for (int ii = 0; ii < 8; ii++)
#pragma unroll
            for (int jj = 0; jj < 4; jj++)
                acc[ii][jj] = ffma2(ap[ii], bb[jj], acc[ii][jj]);
    }
    __syncthreads();   // everyone done reading Bs (G)

    // Write V2 transposed: Vt[j][l]  (columns = f32x2 lanes)
#pragma unroll
    for (int jp = 0; jp < 4; jp++) {
        float2 vv[8];
#pragma unroll
        for (int ii = 0; ii < 8; ii++) vv[ii] = unpk(acc[ii][jp]);
        int jc = j0 + 2 * jp;
        *(float4*)&Vt[jc * SMS + l0]           = make_float4(vv[0].x, vv[1].x, vv[2].x, vv[3].x);
        *(float4*)&Vt[jc * SMS + l0 + 4]       = make_float4(vv[4].x, vv[5].x, vv[6].x, vv[7].x);
        *(float4*)&Vt[(jc + 1) * SMS + l0]     = make_float4(vv[0].y, vv[1].y, vv[2].y, vv[3].y);
        *(float4*)&Vt[(jc + 1) * SMS + l0 + 4] = make_float4(vv[4].y, vv[5].y, vv[6].y, vv[7].y);
    }
    // Load W2t into Bs
#pragma unroll
    for (int q = 0; q < 16; q++) {
        int idx = t + 256 * q;
        int r = idx >> 5, c4 = idx & 31;
        *(float4*)&Bs[r * SMS + c4 * 4] = ((const float4*)g_w2t)[idx];
    }
    __syncthreads();

    // Stage 2: out[l][p] = num/max(sqrt(n1*n2),eps), three packed GEMM accs
    // sharing one K loop. Two ROW phases (4 rows x 8 p x 3 accs each).
    float* outbase = out + ((size_t)g * LL + (size_t)tile * 128) * DD;
    int p0 = tx * 8;
#pragma unroll 1
    for (int ph = 0; ph < 2; ph++) {
        int r0 = ty * 8 + ph * 4;
        u64 aN[4][4], a1[4][4], a2[4][4];
#pragma unroll
        for (int i = 0; i < 4; i++)
#pragma unroll
            for (int j = 0; j < 4; j++) { aN[i][j] = 0ull; a1[i][j] = 0ull; a2[i][j] = 0ull; }

#pragma unroll 2
        for (int k = 0; k < 128; k++) {
            float4 xv = *(const float4*)&Xt[k * SMS + r0];
            float4 vv = *(const float4*)&Vt[k * SMS + r0];
            ulonglong2 w0 = *(const ulonglong2*)&Bs[k * SMS + p0];
            ulonglong2 w1 = *(const ulonglong2*)&Bs[k * SMS + p0 + 4];
            u64 ww[4] = {w0.x, w0.y, w1.x, w1.y};
            float xa[4] = {xv.x, xv.y, xv.z, xv.w};
            float va[4] = {vv.x, vv.y, vv.z, vv.w};
#pragma unroll
            for (int i = 0; i < 4; i++) {
                u64 xp = pack2(xa[i]);
                u64 vp = pack2(va[i]);
                u64 en = fmul2(xp, vp);
                u64 e1 = fmul2(xp, xp);
                u64 e2 = fmul2(vp, vp);
#pragma unroll
                for (int j = 0; j < 4; j++) {
                    aN[i][j] = ffma2(en, ww[j], aN[i][j]);
                    a1[i][j] = ffma2(e1, ww[j], a1[i][j]);
                    a2[i][j] = ffma2(e2, ww[j], a2[i][j]);
                }
            }
        }

#pragma unroll
        for (int i = 0; i < 4; i++) {
            float o[8];
#pragma unroll
            for (int j = 0; j < 4; j++) {
                float2 n  = unpk(aN[i][j]);
                float2 s1 = unpk(a1[i][j]);
                float2 s2 = unpk(a2[i][j]);
                float d0 = fmaxf(sqrtf(s1.x * s2.x), 1e-8f);
                float d1 = fmaxf(sqrtf(s1.y * s2.y), 1e-8f);
                o[2 * j]     = __fdividef(n.x, d0);
                o[2 * j + 1] = __fdividef(n.y, d1);
            }
            *(float4*)&outbase[(r0 + i) * DD + p0]     = make_float4(o[0], o[1], o[2], o[3]);
            *(float4*)&outbase[(r0 + i) * DD + p0 + 4] = make_float4(o[4], o[5], o[6], o[7]);
        }
    }
}

// ---------------------------------------------------------------------------
extern "C" void kernel_launch(void* const* d_in, const int* in_sizes, int n_in,
                              void* d_out, int out_size) {
    const float* feats = (const float*)d_in[0];
    const float* mp_w  = (const float*)d_in[1];
    float* out = (float*)d_out;

    cudaFuncSetAttribute(fused_kernel, cudaFuncAttributeMaxDynamicSharedMemorySize,
                         FUSED_SMEM);

    w2_kernel<<<64, 256>>>(mp_w);
    gram_kernel<<<NG * NSPLIT, 256>>>(feats);
    reduce_kernel<<<(NG * DD * DD) / 256, 256>>>();
    fused_kernel<<<NG * (LL / 128), 256, FUSED_SMEM>>>(feats, out);
}

// round 8
// speedup vs baseline: 3.1873x; 3.0944x over previous
#include <cuda_runtime.h>
#include <cuda_bf16.h>
#include <cstdint>

// Problem constants: 64 graph-sides x 2048 rows x 128 dim.
#define NG 64
#define LL 2048
#define DD 128

typedef unsigned int u32;

__device__ __forceinline__ u32 s2u(const void* p) {
    u32 a; asm("{ .reg .u64 t; cvta.to.shared.u64 t, %1; cvt.u32.u64 %0, t; }" : "=r"(a) : "l"(p)); return a;
}
// 128x128 bf16 tile, 256B rows, 16B-chunk XOR swizzle (conflict-free ldmatrix).
__device__ __forceinline__ u32 phys(u32 r, u32 c) { return r * 256u + (((c ^ (r & 7u)) << 4)); }

__device__ __forceinline__ void ldm4(u32* r, u32 a) {
    asm volatile("ldmatrix.sync.aligned.m8n8.x4.shared.b16 {%0,%1,%2,%3}, [%4];"
                 : "=r"(r[0]), "=r"(r[1]), "=r"(r[2]), "=r"(r[3]) : "r"(a));
}
__device__ __forceinline__ void ldm4t(u32* r, u32 a) {
    asm volatile("ldmatrix.sync.aligned.m8n8.x4.trans.shared.b16 {%0,%1,%2,%3}, [%4];"
                 : "=r"(r[0]), "=r"(r[1]), "=r"(r[2]), "=r"(r[3]) : "r"(a));
}
__device__ __forceinline__ void mma16816(float* c, const u32* a, u32 b0, u32 b1) {
    asm volatile("mma.sync.aligned.m16n8k16.row.col.f32.bf16.bf16.f32 "
        "{%0,%1,%2,%3}, {%4,%5,%6,%7}, {%8,%9}, {%0,%1,%2,%3};"
        : "+f"(c[0]), "+f"(c[1]), "+f"(c[2]), "+f"(c[3])
        : "r"(a[0]), "r"(a[1]), "r"(a[2]), "r"(a[3]), "r"(b0), "r"(b1));
}

__device__ __forceinline__ u32 pk(float a, float b) {
    __nv_bfloat162 t = __floats2bfloat162_rn(a, b); return *(u32*)&t;
}
__device__ __forceinline__ float2 upk(u32 v) {
    return __bfloat1622float2(*(__nv_bfloat162*)&v);
}

// Scratch (plain row-major in gmem; swizzle applied at smem staging)
__device__ float g_gram_part[NG][2][DD * DD];
__device__ __align__(16) __nv_bfloat16 g_gimgH[NG][DD * DD];
__device__ __align__(16) __nv_bfloat16 g_gimgL[NG][DD * DD];
__device__ __align__(16) __nv_bfloat16 g_w2H[DD * DD];
__device__ __align__(16) __nv_bfloat16 g_w2L[DD * DD];

// ---------------------------------------------------------------------------
// Kernel 1: W2 = mp_w^2, split hi/lo
// ---------------------------------------------------------------------------
__global__ void w2img_kernel(const float* __restrict__ mp_w) {
    int idx = blockIdx.x * blockDim.x + threadIdx.x;
    if (idx < DD * DD) {
        float w = mp_w[idx];
        float f = w * w;
        __nv_bfloat16 h = __float2bfloat16(f);
        g_w2H[idx] = h;
        g_w2L[idx] = __float2bfloat16(f - __bfloat162float(h));
    }
}

// ---------------------------------------------------------------------------
// Kernel 2: Gram partials.  CTA = (side, K-half). C = X^T X over 1024 rows.
// Chunks of 128 rows staged natural [l][i] (split bf16); ldmatrix.trans gives
// X^T fragments for both A and B. 3-term split accumulation in fp32.
// ---------------------------------------------------------------------------
__global__ void __launch_bounds__(256) gram_kernel(const float* __restrict__ feats) {
    extern __shared__ __align__(16) unsigned char sm[];
    unsigned char* SH = sm;
    unsigned char* SL = sm + 32768;
    u32 sSH = s2u(sm), sSL = sSH + 32768;

    int side = blockIdx.x >> 1, half = blockIdx.x & 1;
    int t = threadIdx.x, wid = t >> 5, lane = t & 31;
    const float4* X = (const float4*)(feats + ((size_t)side * LL + (size_t)half * 1024) * DD);

    float acc[16][4];
#pragma unroll
    for (int i = 0; i < 16; i++) { acc[i][0] = acc[i][1] = acc[i][2] = acc[i][3] = 0.f; }

    float4 pv[16];
#pragma unroll
    for (int q = 0; q < 16; q++) pv[q] = X[t + 256 * q];

    int m0 = wid * 16;
    // A (trans): row = ks*16 + (lane&7) + ((lane>>4)&1)*8 ; chunk = m0/8 + ((lane>>3)&1)
    u32 a_radd = (u32)((lane & 7) + ((lane >> 4) & 1) * 8);
    u32 a_c    = (u32)(m0 >> 3) + (u32)((lane >> 3) & 1);
    // B (trans): row = ks*16 + (lane&7) + ((lane>>3)&1)*8 ; chunk = n0/8 + (lane>>4)
    u32 b_radd = (u32)((lane & 7) + ((lane >> 3) & 1) * 8);
    u32 b_cadd = (u32)(lane >> 4);

    for (int c = 0; c < 8; c++) {
        __syncthreads();     // previous compute done with smem
#pragma unroll
        for (int q = 0; q < 16; q++) {
            u32 r = (u32)(wid + 8 * q);
            u32 off = phys(r, (u32)(lane >> 1)) + (u32)(lane & 1) * 8u;
            float4 v = pv[q];
            u32 h0 = pk(v.x, v.y), h1 = pk(v.z, v.w);
            float2 f0 = upk(h0), f1 = upk(h1);
            u32 l0 = pk(v.x - f0.x, v.y - f0.y), l1 = pk(v.z - f1.x, v.w - f1.y);
            *(uint2*)(SH + off) = make_uint2(h0, h1);
            *(uint2*)(SL + off) = make_uint2(l0, l1);
        }
        __syncthreads();
        if (c < 7) {   // prefetch next chunk; latency overlaps compute
            const float4* Xn = X + (size_t)(c + 1) * 4096;
#pragma unroll
            for (int q = 0; q < 16; q++) pv[q] = Xn[t + 256 * q];
        }
#pragma unroll
        for (int ks = 0; ks < 8; ks++) {
            u32 aH[4], aL[4];
            u32 ar = (u32)(ks * 16) + a_radd;
            ldm4t(aH, sSH + phys(ar, a_c));
            ldm4t(aL, sSL + phys(ar, a_c));
            u32 br = (u32)(ks * 16) + b_radd;
#pragma unroll
            for (int np = 0; np < 8; np++) {
                u32 bH[4], bL[4];
                u32 bc = (u32)(np * 2) + b_cadd;
                ldm4t(bH, sSH + phys(br, bc));
                ldm4t(bL, sSL + phys(br, bc));
                mma16816(acc[2 * np],     aH, bH[0], bH[1]);
                mma16816(acc[2 * np],     aH, bL[0], bL[1]);
                mma16816(acc[2 * np],     aL, bH[0], bH[1]);
                mma16816(acc[2 * np + 1], aH, bH[2], bH[3]);
                mma16816(acc[2 * np + 1], aH, bL[2], bL[3]);
                mma16816(acc[2 * np + 1], aL, bH[2], bH[3]);
            }
        }
    }
    float* dst = g_gram_part[side][half];
    int r0 = m0 + (lane >> 2);
    int j0 = 2 * (lane & 3);
#pragma unroll
    for (int nt = 0; nt < 16; nt++) {
        int j = j0 + 8 * nt;
        *(float2*)&dst[r0 * DD + j]       = make_float2(acc[nt][0], acc[nt][1]);
        *(float2*)&dst[(r0 + 8) * DD + j] = make_float2(acc[nt][2], acc[nt][3]);
    }
}

// ---------------------------------------------------------------------------
// Kernel 3: reduce partials + split hi/lo
// ---------------------------------------------------------------------------
__global__ void reduce_split_kernel() {
    int idx = blockIdx.x * blockDim.x + threadIdx.x;
    int s = idx >> 14, e = idx & 16383;
    float v = g_gram_part[s][0][e] + g_gram_part[s][1][e];
    __nv_bfloat16 h = __float2bfloat16(v);
    g_gimgH[s][e] = h;
    g_gimgL[s][e] = __float2bfloat16(v - __bfloat162float(h));
}

// ---------------------------------------------------------------------------
// Kernel 4: fused  V2 = X·G_partner -> E build (in-register) -> match GEMMs
// smem: XH XL (X, later E1=x^2 / E2=v^2), BH BL (G, later E0=x*v hi/lo), WH WL.
// ---------------------------------------------------------------------------
#define FUSED_SMEM (6 * 32768)

__global__ void __launch_bounds__(256) fused_kernel(const float* __restrict__ feats,
                                                    float* __restrict__ out) {
    extern __shared__ __align__(16) unsigned char sm[];
    unsigned char* XH = sm;
    unsigned char* XL = sm + 32768;
    unsigned char* BH = sm + 65536;
    unsigned char* BL = sm + 98304;
    unsigned char* WH = sm + 131072;
    unsigned char* WL = sm + 163840;
    u32 sXH = s2u(sm), sXL = sXH + 32768;
    u32 sBH = sXH + 65536, sBL = sXH + 98304;
    u32 sWH = sXH + 131072, sWL = sXH + 163840;

    int blk = blockIdx.x, g = blk >> 4, tile = blk & 15;
    int t = threadIdx.x, wid = t >> 5, lane = t & 31;
    size_t lbase = (size_t)g * LL + (size_t)tile * 128;

    // ---- stage: X (split), G (partner), W2
    {
        const float4* xs = (const float4*)(feats + lbase * DD);
#pragma unroll
        for (int q = 0; q < 16; q++) {
            int idx = t + 256 * q;
            u32 r = (u32)(idx >> 5);
            u32 ln = (u32)(idx & 31);
            u32 off = phys(r, ln >> 1) + (ln & 1) * 8u;
            float4 v = xs[idx];
            u32 h0 = pk(v.x, v.y), h1 = pk(v.z, v.w);
            float2 f0 = upk(h0), f1 = upk(h1);
            u32 l0 = pk(v.x - f0.x, v.y - f0.y), l1 = pk(v.z - f1.x, v.w - f1.y);
            *(uint2*)(XH + off) = make_uint2(h0, h1);
            *(uint2*)(XL + off) = make_uint2(l0, l1);
        }
        const uint4* gh = (const uint4*)&g_gimgH[g ^ 1][0];
        const uint4* gl = (const uint4*)&g_gimgL[g ^ 1][0];
        const uint4* wh = (const uint4*)&g_w2H[0];
        const uint4* wl = (const uint4*)&g_w2L[0];
#pragma unroll
        for (int q = 0; q < 8; q++) {
            int idx = t + 256 * q;
            u32 r = (u32)(idx >> 4), ch = (u32)(idx & 15);
            u32 off = phys(r, ch);
            *(uint4*)(BH + off) = gh[idx];
            *(uint4*)(BL + off) = gl[idx];
            *(uint4*)(WH + off) = wh[idx];
            *(uint4*)(WL + off) = wl[idx];
        }
    }
    __syncthreads();

    int m0 = wid * 16;
    u32 aA_r = (u32)m0 + (u32)(lane & 15);
    u32 aA_c = (u32)(lane >> 4);
    u32 bB_radd = (u32)((lane & 7) + (lane >> 4) * 8);
    u32 bB_cadd = (u32)((lane >> 3) & 1);

    // ---- GEMM1: V = X · G (3-term split)
    float vac[16][4];
#pragma unroll
    for (int i = 0; i < 16; i++) { vac[i][0] = vac[i][1] = vac[i][2] = vac[i][3] = 0.f; }
#pragma unroll
    for (int ks = 0; ks < 8; ks++) {
        u32 aH[4], aL[4];
        u32 ac = (u32)(ks * 2) + aA_c;
        ldm4(aH, sXH + phys(aA_r, ac));
        ldm4(aL, sXL + phys(aA_r, ac));
        u32 bc = (u32)(ks * 2) + bB_cadd;
#pragma unroll
        for (int np = 0; np < 8; np++) {
            u32 br = (u32)(np * 16) + bB_radd;
            u32 bH[4], bL[4];
            ldm4(bH, sBH + phys(br, bc));
            ldm4(bL, sBL + phys(br, bc));
            mma16816(vac[2 * np],     aH, bH[0], bH[1]);
            mma16816(vac[2 * np],     aH, bL[0], bL[1]);
            mma16816(vac[2 * np],     aL, bH[0], bH[1]);
            mma16816(vac[2 * np + 1], aH, bH[2], bH[3]);
            mma16816(vac[2 * np + 1], aH, bL[2], bL[3]);
            mma16816(vac[2 * np + 1], aL, bH[2], bH[3]);
        }
    }
    __syncthreads();   // all GEMM1 smem reads complete before E overwrites

    // ---- E build: each thread owns exactly the elements it reads & writes.
    {
        u32 r = (u32)m0 + (u32)(lane >> 2);
        u32 sub = 4u * (u32)(lane & 3);
#pragma unroll
        for (int nt = 0; nt < 16; nt++) {
            u32 offA = phys(r, (u32)nt) + sub;        // (r+8)&7 == r&7 -> same xor
            u32 offB = phys(r + 8, (u32)nt) + sub;
            {
                float2 xh = upk(*(u32*)(XH + offA));
                float2 xl = upk(*(u32*)(XL + offA));
                float x0 = xh.x + xl.x, x1 = xh.y + xl.y;
                float v0 = vac[nt][0], v1 = vac[nt][1];
                float e0 = x0 * v0, e1 = x1 * v1;
                u32 h = pk(e0, e1); float2 hf = upk(h);
                *(u32*)(BH + offA) = h;
                *(u32*)(BL + offA) = pk(e0 - hf.x, e1 - hf.y);
                *(u32*)(XH + offA) = pk(x0 * x0, x1 * x1);
                *(u32*)(XL + offA) = pk(v0 * v0, v1 * v1);
            }
            {
                float2 xh = upk(*(u32*)(XH + offB));
                float2 xl = upk(*(u32*)(XL + offB));
                float x0 = xh.x + xl.x, x1 = xh.y + xl.y;
                float v0 = vac[nt][2], v1 = vac[nt][3];
                float e0 = x0 * v0, e1 = x1 * v1;
                u32 h = pk(e0, e1); float2 hf = upk(h);
                *(u32*)(BH + offB) = h;
                *(u32*)(BL + offB) = pk(e0 - hf.x, e1 - hf.y);
                *(u32*)(XH + offB) = pk(x0 * x0, x1 * x1);
                *(u32*)(XL + offB) = pk(v0 * v0, v1 * v1);
            }
        }
    }
    __syncthreads();

    // ---- GEMM2 (+fused epilogue), two n-halves of the perspective dim
    float* outp = out + lbase * DD;
    int r0 = m0 + (lane >> 2);
#pragma unroll 1
    for (int nh = 0; nh < 2; nh++) {
        float aN[8][4], a1[8][4], a2[8][4];
#pragma unroll
        for (int i = 0; i < 8; i++) {
            aN[i][0] = aN[i][1] = aN[i][2] = aN[i][3] = 0.f;
            a1[i][0] = a1[i][1] = a1[i][2] = a1[i][3] = 0.f;
            a2[i][0] = a2[i][1] = a2[i][2] = a2[i][3] = 0.f;
        }
#pragma unroll
        for (int ks = 0; ks < 8; ks++) {
            u32 ac = (u32)(ks * 2) + aA_c;
            u32 aoff = phys(aA_r, ac);
            u32 e0h[4], e0l[4], e1f[4], e2f[4];
            ldm4(e0h, sBH + aoff);
            ldm4(e0l, sBL + aoff);
            ldm4(e1f, sXH + aoff);
            ldm4(e2f, sXL + aoff);
            u32 bc = (u32)(ks * 2) + bB_cadd;
#pragma unroll
            for (int np = 0; np < 4; np++) {
                u32 br = (u32)(nh * 64 + np * 16) + bB_radd;
                u32 wh[4], wl[4];
                ldm4(wh, sWH + phys(br, bc));
                ldm4(wl, sWL + phys(br, bc));
                // n-tile 2*np
                mma16816(aN[2 * np], e0h, wh[0], wh[1]);
                mma16816(aN[2 * np], e0l, wh[0], wh[1]);
                mma16816(aN[2 * np], e0h, wl[0], wl[1]);
                mma16816(a1[2 * np], e1f, wh[0], wh[1]);
                mma16816(a1[2 * np], e1f, wl[0], wl[1]);
                mma16816(a2[2 * np], e2f, wh[0], wh[1]);
                mma16816(a2[2 * np], e2f, wl[0], wl[1]);
                // n-tile 2*np+1
                mma16816(aN[2 * np + 1], e0h, wh[2], wh[3]);
                mma16816(aN[2 * np + 1], e0l, wh[2], wh[3]);
                mma16816(aN[2 * np + 1], e0h, wl[2], wl[3]);
                mma16816(a1[2 * np + 1], e1f, wh[2], wh[3]);
                mma16816(a1[2 * np + 1], e1f, wl[2], wl[3]);
                mma16816(a2[2 * np + 1], e2f, wh[2], wh[3]);
                mma16816(a2[2 * np + 1], e2f, wl[2], wl[3]);
            }
        }
#pragma unroll
        for (int nt = 0; nt < 8; nt++) {
            int p0 = nh * 64 + nt * 8 + 2 * (lane & 3);
            float d0 = fmaxf(sqrtf(a1[nt][0] * a2[nt][0]), 1e-8f);
            float d1 = fmaxf(sqrtf(a1[nt][1] * a2[nt][1]), 1e-8f);
            float d2 = fmaxf(sqrtf(a1[nt][2] * a2[nt][2]), 1e-8f);
            float d3 = fmaxf(sqrtf(a1[nt][3] * a2[nt][3]), 1e-8f);
            *(float2*)&outp[(size_t)r0 * DD + p0] =
                make_float2(__fdividef(aN[nt][0], d0), __fdividef(aN[nt][1], d1));
            *(float2*)&outp[(size_t)(r0 + 8) * DD + p0] =
                make_float2(__fdividef(aN[nt][2], d2), __fdividef(aN[nt][3], d3));
        }
    }
}

// ---------------------------------------------------------------------------
extern "C" void kernel_launch(void* const* d_in, const int* in_sizes, int n_in,
                              void* d_out, int out_size) {
    const float* feats = (const float*)d_in[0];
    const float* mp_w  = (const float*)d_in[1];
    float* out = (float*)d_out;

    cudaFuncSetAttribute(gram_kernel,  cudaFuncAttributeMaxDynamicSharedMemorySize, 65536);
    cudaFuncSetAttribute(fused_kernel, cudaFuncAttributeMaxDynamicSharedMemorySize, FUSED_SMEM);

    w2img_kernel<<<64, 256>>>(mp_w);
    gram_kernel<<<NG * 2, 256, 65536>>>(feats);
    reduce_split_kernel<<<(NG * DD * DD) / 256, 256>>>();
    fused_kernel<<<NG * (LL / 128), 256, FUSED_SMEM>>>(feats, out);
}

// round 10
// speedup vs baseline: 4.0167x; 1.2602x over previous
#include <cuda_runtime.h>
#include <cuda_bf16.h>
#include <cstdint>

// Problem constants: 64 graph-sides x 2048 rows x 128 dim.
#define NG 64
#define LL 2048
#define DD 128

typedef unsigned int u32;

__device__ __forceinline__ u32 s2u(const void* p) {
    u32 a; asm("{ .reg .u64 t; cvta.to.shared.u64 t, %1; cvt.u32.u64 %0, t; }" : "=r"(a) : "l"(p)); return a;
}
// 128x128 bf16 tile, 256B rows, 16B-chunk XOR swizzle (conflict-free ldmatrix).
__device__ __forceinline__ u32 phys(u32 r, u32 c) { return r * 256u + (((c ^ (r & 7u)) << 4)); }

__device__ __forceinline__ void ldm4(u32* r, u32 a) {
    asm volatile("ldmatrix.sync.aligned.m8n8.x4.shared.b16 {%0,%1,%2,%3}, [%4];"
                 : "=r"(r[0]), "=r"(r[1]), "=r"(r[2]), "=r"(r[3]) : "r"(a));
}
__device__ __forceinline__ void ldm4t(u32* r, u32 a) {
    asm volatile("ldmatrix.sync.aligned.m8n8.x4.trans.shared.b16 {%0,%1,%2,%3}, [%4];"
                 : "=r"(r[0]), "=r"(r[1]), "=r"(r[2]), "=r"(r[3]) : "r"(a));
}
__device__ __forceinline__ void mma16816(float* c, const u32* a, u32 b0, u32 b1) {
    asm volatile("mma.sync.aligned.m16n8k16.row.col.f32.bf16.bf16.f32 "
        "{%0,%1,%2,%3}, {%4,%5,%6,%7}, {%8,%9}, {%0,%1,%2,%3};"
        : "+f"(c[0]), "+f"(c[1]), "+f"(c[2]), "+f"(c[3])
        : "r"(a[0]), "r"(a[1]), "r"(a[2]), "r"(a[3]), "r"(b0), "r"(b1));
}

__device__ __forceinline__ u32 pk(float a, float b) {
    __nv_bfloat162 t = __floats2bfloat162_rn(a, b); return *(u32*)&t;
}
__device__ __forceinline__ float2 upk(u32 v) {
    return __bfloat1622float2(*(__nv_bfloat162*)&v);
}

// Scratch (plain row-major in gmem; swizzle applied at smem staging)
__device__ float g_gram_part[NG][2][DD * DD];
__device__ __align__(16) __nv_bfloat16 g_gimgH[NG][DD * DD];
__device__ __align__(16) __nv_bfloat16 g_gimgL[NG][DD * DD];
__device__ __align__(16) __nv_bfloat16 g_w2H[DD * DD];

// ---------------------------------------------------------------------------
// Kernel 1: W2 = mp_w^2, hi image only (consistent-weight perturbation)
// ---------------------------------------------------------------------------
__global__ void w2img_kernel(const float* __restrict__ mp_w) {
    int idx = blockIdx.x * blockDim.x + threadIdx.x;
    if (idx < DD * DD) {
        float w = mp_w[idx];
        g_w2H[idx] = __float2bfloat16(w * w);
    }
}

// ---------------------------------------------------------------------------
// Kernel 2: Gram partials.  CTA = (side, K-half). C = Xh^T (Xh + Xl), 2-term.
// ---------------------------------------------------------------------------
__global__ void __launch_bounds__(256) gram_kernel(const float* __restrict__ feats) {
    extern __shared__ __align__(16) unsigned char sm[];
    unsigned char* SH = sm;
    unsigned char* SL = sm + 32768;
    u32 sSH = s2u(sm), sSL = sSH + 32768;

    int side = blockIdx.x >> 1, half = blockIdx.x & 1;
    int t = threadIdx.x, wid = t >> 5, lane = t & 31;
    const float4* X = (const float4*)(feats + ((size_t)side * LL + (size_t)half * 1024) * DD);

    float acc[16][4];
#pragma unroll
    for (int i = 0; i < 16; i++) { acc[i][0] = acc[i][1] = acc[i][2] = acc[i][3] = 0.f; }

    float4 pv[16];
#pragma unroll
    for (int q = 0; q < 16; q++) pv[q] = X[t + 256 * q];

    int m0 = wid * 16;
    u32 a_radd = (u32)((lane & 7) + ((lane >> 4) & 1) * 8);
    u32 a_c    = (u32)(m0 >> 3) + (u32)((lane >> 3) & 1);
    u32 b_radd = (u32)((lane & 7) + ((lane >> 3) & 1) * 8);
    u32 b_cadd = (u32)(lane >> 4);

    for (int c = 0; c < 8; c++) {
        __syncthreads();     // previous compute done with smem
#pragma unroll
        for (int q = 0; q < 16; q++) {
            u32 r = (u32)(wid + 8 * q);
            u32 off = phys(r, (u32)(lane >> 1)) + (u32)(lane & 1) * 8u;
            float4 v = pv[q];
            u32 h0 = pk(v.x, v.y), h1 = pk(v.z, v.w);
            float2 f0 = upk(h0), f1 = upk(h1);
            u32 l0 = pk(v.x - f0.x, v.y - f0.y), l1 = pk(v.z - f1.x, v.w - f1.y);
            *(uint2*)(SH + off) = make_uint2(h0, h1);
            *(uint2*)(SL + off) = make_uint2(l0, l1);
        }
        __syncthreads();
        if (c < 7) {   // prefetch next chunk; latency overlaps compute
            const float4* Xn = X + (size_t)(c + 1) * 4096;
#pragma unroll
            for (int q = 0; q < 16; q++) pv[q] = Xn[t + 256 * q];
        }
#pragma unroll
        for (int ks = 0; ks < 8; ks++) {
            u32 aH[4];
            u32 ar = (u32)(ks * 16) + a_radd;
            ldm4t(aH, sSH + phys(ar, a_c));
            u32 br = (u32)(ks * 16) + b_radd;
#pragma unroll
            for (int np = 0; np < 8; np++) {
                u32 bH[4], bL[4];
                u32 bc = (u32)(np * 2) + b_cadd;
                ldm4t(bH, sSH + phys(br, bc));
                ldm4t(bL, sSL + phys(br, bc));
                mma16816(acc[2 * np],     aH, bH[0], bH[1]);
                mma16816(acc[2 * np],     aH, bL[0], bL[1]);
                mma16816(acc[2 * np + 1], aH, bH[2], bH[3]);
                mma16816(acc[2 * np + 1], aH, bL[2], bL[3]);
            }
        }
    }
    float* dst = g_gram_part[side][half];
    int r0 = m0 + (lane >> 2);
    int j0 = 2 * (lane & 3);
#pragma unroll
    for (int nt = 0; nt < 16; nt++) {
        int j = j0 + 8 * nt;
        *(float2*)&dst[r0 * DD + j]       = make_float2(acc[nt][0], acc[nt][1]);
        *(float2*)&dst[(r0 + 8) * DD + j] = make_float2(acc[nt][2], acc[nt][3]);
    }
}

// ---------------------------------------------------------------------------
// Kernel 3: reduce partials + split hi/lo
// ---------------------------------------------------------------------------
__global__ void reduce_split_kernel() {
    int idx = blockIdx.x * blockDim.x + threadIdx.x;
    int s = idx >> 14, e = idx & 16383;
    float v = g_gram_part[s][0][e] + g_gram_part[s][1][e];
    __nv_bfloat16 h = __float2bfloat16(v);
    g_gimgH[s][e] = h;
    g_gimgL[s][e] = __float2bfloat16(v - __bfloat162float(h));
}

// ---------------------------------------------------------------------------
// Kernel 4: fused  V2 = Xh·G_partner -> E build (in-register) -> match GEMMs
// smem: XH XL (X, later E1=x^2 / E2=v^2), BH BL (G, later E0=x*v hi/lo), WH.
// ---------------------------------------------------------------------------
#define FUSED_SMEM (5 * 32768)

__global__ void __launch_bounds__(256) fused_kernel(const float* __restrict__ feats,
                                                    float* __restrict__ out) {
    extern __shared__ __align__(16) unsigned char sm[];
    unsigned char* XH = sm;
    unsigned char* XL = sm + 32768;
    unsigned char* BH = sm + 65536;
    unsigned char* BL = sm + 98304;
    unsigned char* WH = sm + 131072;
    u32 sXH = s2u(sm), sXL = sXH + 32768;
    u32 sBH = sXH + 65536, sBL = sXH + 98304;
    u32 sWH = sXH + 131072;

    int blk = blockIdx.x, g = blk >> 4, tile = blk & 15;
    int t = threadIdx.x, wid = t >> 5, lane = t & 31;
    size_t lbase = (size_t)g * LL + (size_t)tile * 128;

    // ---- stage: X (split), G (partner, split), W2 (hi only)
    {
        const float4* xs = (const float4*)(feats + lbase * DD);
#pragma unroll
        for (int q = 0; q < 16; q++) {
            int idx = t + 256 * q;
            u32 r = (u32)(idx >> 5);
            u32 ln = (u32)(idx & 31);
            u32 off = phys(r, ln >> 1) + (ln & 1) * 8u;
            float4 v = xs[idx];
            u32 h0 = pk(v.x, v.y), h1 = pk(v.z, v.w);
            float2 f0 = upk(h0), f1 = upk(h1);
            u32 l0 = pk(v.x - f0.x, v.y - f0.y), l1 = pk(v.z - f1.x, v.w - f1.y);
            *(uint2*)(XH + off) = make_uint2(h0, h1);
            *(uint2*)(XL + off) = make_uint2(l0, l1);
        }
        const uint4* gh = (const uint4*)&g_gimgH[g ^ 1][0];
        const uint4* gl = (const uint4*)&g_gimgL[g ^ 1][0];
        const uint4* wh = (const uint4*)&g_w2H[0];
#pragma unroll
        for (int q = 0; q < 8; q++) {
            int idx = t + 256 * q;
            u32 r = (u32)(idx >> 4), ch = (u32)(idx & 15);
            u32 off = phys(r, ch);
            *(uint4*)(BH + off) = gh[idx];
            *(uint4*)(BL + off) = gl[idx];
            *(uint4*)(WH + off) = wh[idx];
        }
    }
    __syncthreads();

    int m0 = wid * 16;
    u32 aA_r = (u32)m0 + (u32)(lane & 15);
    u32 aA_c = (u32)(lane >> 4);
    u32 bB_radd = (u32)((lane & 7) + (lane >> 4) * 8);
    u32 bB_cadd = (u32)((lane >> 3) & 1);

    // ---- GEMM1: V = Xh · (Gh + Gl)   (2-term)
    float vac[16][4];
#pragma unroll
    for (int i = 0; i < 16; i++) { vac[i][0] = vac[i][1] = vac[i][2] = vac[i][3] = 0.f; }
#pragma unroll
    for (int ks = 0; ks < 8; ks++) {
        u32 aH[4];
        u32 ac = (u32)(ks * 2) + aA_c;
        ldm4(aH, sXH + phys(aA_r, ac));
        u32 bc = (u32)(ks * 2) + bB_cadd;
#pragma unroll
        for (int np = 0; np < 8; np++) {
            u32 br = (u32)(np * 16) + bB_radd;
            u32 bH[4], bL[4];
            ldm4(bH, sBH + phys(br, bc));
            ldm4(bL, sBL + phys(br, bc));
            mma16816(vac[2 * np],     aH, bH[0], bH[1]);
            mma16816(vac[2 * np],     aH, bL[0], bL[1]);
            mma16816(vac[2 * np + 1], aH, bH[2], bH[3]);
            mma16816(vac[2 * np + 1], aH, bL[2], bL[3]);
        }
    }
    __syncthreads();   // all GEMM1 smem reads complete before E overwrites

    // ---- E build: each thread owns exactly the elements it reads & writes.
    // E0 (x*v) split -> BH/BL ; E1 (x^2) -> XH ; E2 (v^2) -> XL.
    {
        u32 r = (u32)m0 + (u32)(lane >> 2);
        u32 sub = 4u * (u32)(lane & 3);
#pragma unroll
        for (int nt = 0; nt < 16; nt++) {
            u32 offA = phys(r, (u32)nt) + sub;        // (r+8)&7 == r&7 -> same xor
            u32 offB = phys(r + 8, (u32)nt) + sub;
            {
                float2 xh = upk(*(u32*)(XH + offA));
                float2 xl = upk(*(u32*)(XL + offA));
                float x0 = xh.x + xl.x, x1 = xh.y + xl.y;
                float v0 = vac[nt][0], v1 = vac[nt][1];
                float e0 = x0 * v0, e1 = x1 * v1;
                u32 h = pk(e0, e1); float2 hf = upk(h);
                *(u32*)(BH + offA) = h;
                *(u32*)(BL + offA) = pk(e0 - hf.x, e1 - hf.y);
                *(u32*)(XH + offA) = pk(x0 * x0, x1 * x1);
                *(u32*)(XL + offA) = pk(v0 * v0, v1 * v1);
            }
            {
                float2 xh = upk(*(u32*)(XH + offB));
                float2 xl = upk(*(u32*)(XL + offB));
                float x0 = xh.x + xl.x, x1 = xh.y + xl.y;
                float v0 = vac[nt][2], v1 = vac[nt][3];
                float e0 = x0 * v0, e1 = x1 * v1;
                u32 h = pk(e0, e1); float2 hf = upk(h);
                *(u32*)(BH + offB) = h;
                *(u32*)(BL + offB) = pk(e0 - hf.x, e1 - hf.y);
                *(u32*)(XH + offB) = pk(x0 * x0, x1 * x1);
                *(u32*)(XL + offB) = pk(v0 * v0, v1 * v1);
            }
        }
    }
    __syncthreads();

    // ---- GEMM2 (+fused epilogue), W2 hi-only; num 2-term, n1/n2 1-term
    float* outp = out + lbase * DD;
    int r0 = m0 + (lane >> 2);
#pragma unroll 1
    for (int nh = 0; nh < 2; nh++) {
        float aN[8][4], a1[8][4], a2[8][4];
#pragma unroll
        for (int i = 0; i < 8; i++) {
            aN[i][0] = aN[i][1] = aN[i][2] = aN[i][3] = 0.f;
            a1[i][0] = a1[i][1] = a1[i][2] = a1[i][3] = 0.f;
            a2[i][0] = a2[i][1] = a2[i][2] = a2[i][3] = 0.f;
        }
#pragma unroll
        for (int ks = 0; ks < 8; ks++) {
            u32 ac = (u32)(ks * 2) + aA_c;
            u32 aoff = phys(aA_r, ac);
            u32 e0h[4], e0l[4], e1f[4], e2f[4];
            ldm4(e0h, sBH + aoff);
            ldm4(e0l, sBL + aoff);
            ldm4(e1f, sXH + aoff);
            ldm4(e2f, sXL + aoff);
            u32 bc = (u32)(ks * 2) + bB_cadd;
#pragma unroll
            for (int np = 0; np < 4; np++) {
                u32 br = (u32)(nh * 64 + np * 16) + bB_radd;
                u32 wh[4];
                ldm4(wh, sWH + phys(br, bc));
                // n-tile 2*np
                mma16816(aN[2 * np], e0h, wh[0], wh[1]);
                mma16816(aN[2 * np], e0l, wh[0], wh[1]);
                mma16816(a1[2 * np], e1f, wh[0], wh[1]);
                mma16816(a2[2 * np], e2f, wh[0], wh[1]);
                // n-tile 2*np+1
                mma16816(aN[2 * np + 1], e0h, wh[2], wh[3]);
                mma16816(aN[2 * np + 1], e0l, wh[2], wh[3]);
                mma16816(a1[2 * np + 1], e1f, wh[2], wh[3]);
                mma16816(a2[2 * np + 1], e2f, wh[2], wh[3]);
            }
        }
#pragma unroll
        for (int nt = 0; nt < 8; nt++) {
            int p0 = nh * 64 + nt * 8 + 2 * (lane & 3);
            float d0 = fmaxf(sqrtf(a1[nt][0] * a2[nt][0]), 1e-8f);
            float d1 = fmaxf(sqrtf(a1[nt][1] * a2[nt][1]), 1e-8f);
            float d2 = fmaxf(sqrtf(a1[nt][2] * a2[nt][2]), 1e-8f);
            float d3 = fmaxf(sqrtf(a1[nt][3] * a2[nt][3]), 1e-8f);
            *(float2*)&outp[(size_t)r0 * DD + p0] =
                make_float2(__fdividef(aN[nt][0], d0), __fdividef(aN[nt][1], d1));
            *(float2*)&outp[(size_t)(r0 + 8) * DD + p0] =
                make_float2(__fdividef(aN[nt][2], d2), __fdividef(aN[nt][3], d3));
        }
    }
}

// ---------------------------------------------------------------------------
extern "C" void kernel_launch(void* const* d_in, const int* in_sizes, int n_in,
                              void* d_out, int out_size) {
    const float* feats = (const float*)d_in[0];
    const float* mp_w  = (const float*)d_in[1];
    float* out = (float*)d_out;

    cudaFuncSetAttribute(gram_kernel,  cudaFuncAttributeMaxDynamicSharedMemorySize, 65536);
    cudaFuncSetAttribute(fused_kernel, cudaFuncAttributeMaxDynamicSharedMemorySize, FUSED_SMEM);

    w2img_kernel<<<64, 256>>>(mp_w);
    gram_kernel<<<NG * 2, 256, 65536>>>(feats);
    reduce_split_kernel<<<(NG * DD * DD) / 256, 256>>>();
    fused_kernel<<<NG * (LL / 128), 256, FUSED_SMEM>>>(feats, out);
}